// round 1
// baseline (speedup 1.0000x reference)
#include <cuda_runtime.h>
#include <math.h>

#define NN 100000
#define EE 3200000
#define NBLK ((NN + 255) / 256)
#define EBLK (EE / 256)

// ---------------- device scratch (static; no allocation allowed) -----------
__device__ int   g_is64;
__device__ int   g_src[EE];
__device__ int   g_dst[EE];
__device__ float g_dinv[NN];            // deg -> dinv in place
__device__ float g_h[NN * 16];          // h1, then z
__device__ float g_agg[NN * 16];        // agg1, then agg_z

// vectorized no-return atomic add (sm_90+ PTX)
__device__ __forceinline__ void red_add_v4(float* addr, float4 v) {
    asm volatile("red.global.add.v4.f32 [%0], {%1, %2, %3, %4};"
                 :: "l"(addr), "f"(v.x), "f"(v.y), "f"(v.z), "f"(v.w)
                 : "memory");
}

// ---------------- edge dtype probe (int64 vs int32) ------------------------
__global__ void k_detect(const long long* e) {
    __shared__ int bad;
    if (threadIdx.x == 0) bad = 0;
    __syncthreads();
    long long v = e[threadIdx.x];   // 256 samples; safe for either dtype
    if (v < 0 || v >= (long long)NN) atomicOr(&bad, 1);
    __syncthreads();
    if (threadIdx.x == 0) g_is64 = bad ? 0 : 1;
}

__global__ void k_convert(const void* eptr) {
    int i = blockIdx.x * 256 + threadIdx.x;
    if (g_is64) {
        const long long* e = (const long long*)eptr;
        g_src[i] = (int)e[i];
        g_dst[i] = (int)e[i + EE];
    } else {
        const int* e = (const int*)eptr;
        g_src[i] = e[i];
        g_dst[i] = e[i + EE];
    }
}

// ---------------- degree / dinv --------------------------------------------
__global__ void k_deg_init() {
    int i = blockIdx.x * 256 + threadIdx.x;
    if (i < NN) g_dinv[i] = 1.0f;   // self loop
}

__global__ void k_deg_acc() {
    int e = blockIdx.x * 256 + threadIdx.x;
    atomicAdd(&g_dinv[g_dst[e]], 1.0f);
}

__global__ void k_rsqrt() {
    int i = blockIdx.x * 256 + threadIdx.x;
    if (i < NN) g_dinv[i] = rsqrtf(g_dinv[i]);
}

// ---------------- GEMM1: h1 = x @ W1  (N x 512) @ (512 x 16) --------------
__global__ void k_gemm1(const float* __restrict__ x, const float* __restrict__ W1) {
    __shared__ float Ws[512 * 16];                 // 32 KB
    for (int i = threadIdx.x; i < 512 * 16; i += 256) Ws[i] = W1[i];
    __syncthreads();

    int node = blockIdx.x * 256 + threadIdx.x;
    if (node >= NN) return;

    float acc[16];
#pragma unroll
    for (int j = 0; j < 16; j++) acc[j] = 0.0f;

    const float4* xr = reinterpret_cast<const float4*>(x + (size_t)node * 512);
#pragma unroll 4
    for (int k4 = 0; k4 < 128; k4++) {
        float4 xv = xr[k4];
        const float* wb = &Ws[(k4 * 4) * 16];
#pragma unroll
        for (int c = 0; c < 4; c++) {
            float xc = (c == 0) ? xv.x : (c == 1) ? xv.y : (c == 2) ? xv.z : xv.w;
            const float4* wr = reinterpret_cast<const float4*>(wb + c * 16);
#pragma unroll
            for (int j4 = 0; j4 < 4; j4++) {
                float4 w = wr[j4];
                acc[j4 * 4 + 0] += xc * w.x;
                acc[j4 * 4 + 1] += xc * w.y;
                acc[j4 * 4 + 2] += xc * w.z;
                acc[j4 * 4 + 3] += xc * w.w;
            }
        }
    }
    float4* hp = reinterpret_cast<float4*>(g_h + (size_t)node * 16);
#pragma unroll
    for (int j4 = 0; j4 < 4; j4++)
        hp[j4] = make_float4(acc[j4 * 4 + 0], acc[j4 * 4 + 1],
                             acc[j4 * 4 + 2], acc[j4 * 4 + 3]);
}

// ---------------- self-loop init: agg[i] = h[i] * dinv[i]^2 ----------------
__global__ void k_selfloop_init() {
    int i = blockIdx.x * 256 + threadIdx.x;
    if (i >= NN) return;
    float di = g_dinv[i];
    float s = di * di;
    const float4* hp = reinterpret_cast<const float4*>(g_h + (size_t)i * 16);
    float4* ap = reinterpret_cast<float4*>(g_agg + (size_t)i * 16);
#pragma unroll
    for (int j4 = 0; j4 < 4; j4++) {
        float4 v = hp[j4];
        ap[j4] = make_float4(v.x * s, v.y * s, v.z * s, v.w * s);
    }
}

// ---------------- edge scatter: agg[d] += h[s] * dinv[s]*dinv[d] -----------
__global__ void k_scatter() {
    int e = blockIdx.x * 256 + threadIdx.x;
    int s = g_src[e];
    int d = g_dst[e];
    float nrm = __ldg(&g_dinv[s]) * __ldg(&g_dinv[d]);
    const float4* hp = reinterpret_cast<const float4*>(g_h + (size_t)s * 16);
    float4 v0 = hp[0], v1 = hp[1], v2 = hp[2], v3 = hp[3];
    float* ap = g_agg + (size_t)d * 16;
    red_add_v4(ap + 0,  make_float4(v0.x * nrm, v0.y * nrm, v0.z * nrm, v0.w * nrm));
    red_add_v4(ap + 4,  make_float4(v1.x * nrm, v1.y * nrm, v1.z * nrm, v1.w * nrm));
    red_add_v4(ap + 8,  make_float4(v2.x * nrm, v2.y * nrm, v2.z * nrm, v2.w * nrm));
    red_add_v4(ap + 12, make_float4(v3.x * nrm, v3.y * nrm, v3.z * nrm, v3.w * nrm));
}

// ---------------- layer-2 prep: z = relu(agg1+b1); h<-z; agg<-z*dinv^2 -----
__global__ void k_prep(const float* __restrict__ b1) {
    int i = blockIdx.x * 256 + threadIdx.x;
    if (i >= NN) return;
    float di = g_dinv[i];
    float s = di * di;
    const float4* ap_in = reinterpret_cast<const float4*>(g_agg + (size_t)i * 16);
    const float4* bp = reinterpret_cast<const float4*>(b1);
    float4* hp = reinterpret_cast<float4*>(g_h + (size_t)i * 16);
    float4* ap = reinterpret_cast<float4*>(g_agg + (size_t)i * 16);
#pragma unroll
    for (int j4 = 0; j4 < 4; j4++) {
        float4 v = ap_in[j4];
        float4 b = __ldg(&bp[j4]);
        float4 z;
        z.x = fmaxf(v.x + b.x, 0.0f);
        z.y = fmaxf(v.y + b.y, 0.0f);
        z.z = fmaxf(v.z + b.z, 0.0f);
        z.w = fmaxf(v.w + b.w, 0.0f);
        hp[j4] = z;
        ap[j4] = make_float4(z.x * s, z.y * s, z.z * s, z.w * s);
    }
}

// ---------------- final: out = log_softmax(agg_z @ W2 + b2) ----------------
__global__ void k_final(const float* __restrict__ W2, const float* __restrict__ b2,
                        float* __restrict__ out) {
    __shared__ float W2s[16 * 40];
    __shared__ float b2s[40];
    for (int i = threadIdx.x; i < 16 * 40; i += 256) W2s[i] = W2[i];
    if (threadIdx.x < 40) b2s[threadIdx.x] = b2[threadIdx.x];
    __syncthreads();

    int node = blockIdx.x * 256 + threadIdx.x;
    if (node >= NN) return;

    float z[16];
    const float4* ap = reinterpret_cast<const float4*>(g_agg + (size_t)node * 16);
#pragma unroll
    for (int j4 = 0; j4 < 4; j4++) {
        float4 v = ap[j4];
        z[j4 * 4 + 0] = v.x; z[j4 * 4 + 1] = v.y;
        z[j4 * 4 + 2] = v.z; z[j4 * 4 + 3] = v.w;
    }

    float acc[40];
#pragma unroll
    for (int j = 0; j < 40; j++) acc[j] = b2s[j];
#pragma unroll
    for (int k = 0; k < 16; k++) {
        float zk = z[k];
        const float* wr = &W2s[k * 40];
#pragma unroll
        for (int j = 0; j < 40; j++) acc[j] += zk * wr[j];
    }

    float m = acc[0];
#pragma unroll
    for (int j = 1; j < 40; j++) m = fmaxf(m, acc[j]);
    float ssum = 0.0f;
#pragma unroll
    for (int j = 0; j < 40; j++) ssum += expf(acc[j] - m);
    float lse = m + logf(ssum);

    float* op = out + (size_t)node * 40;
#pragma unroll
    for (int j = 0; j < 40; j++) op[j] = acc[j] - lse;
}

// ---------------- launcher --------------------------------------------------
extern "C" void kernel_launch(void* const* d_in, const int* in_sizes, int n_in,
                              void* d_out, int out_size) {
    const float* x   = (const float*)d_in[0];
    const void*  ei  = d_in[1];
    const float* W1  = (const float*)d_in[2];
    const float* b1  = (const float*)d_in[3];
    const float* W2  = (const float*)d_in[4];
    const float* b2  = (const float*)d_in[5];
    float* out = (float*)d_out;

    k_detect<<<1, 256>>>((const long long*)ei);
    k_convert<<<EBLK, 256>>>(ei);

    k_deg_init<<<NBLK, 256>>>();
    k_deg_acc<<<EBLK, 256>>>();
    k_rsqrt<<<NBLK, 256>>>();

    k_gemm1<<<NBLK, 256>>>(x, W1);
    k_selfloop_init<<<NBLK, 256>>>();
    k_scatter<<<EBLK, 256>>>();

    k_prep<<<NBLK, 256>>>(b1);
    k_scatter<<<EBLK, 256>>>();

    k_final<<<NBLK, 256>>>(W2, b2, out);
}

// round 2
// speedup vs baseline: 1.5169x; 1.5169x over previous
#include <cuda_runtime.h>
#include <math.h>

#define NN 100000
#define EE 3200000
#define NBLK ((NN + 255) / 256)
#define EBLK (EE / 256)
#define SCAN_B 1024
#define NSCAN ((NN + SCAN_B - 1) / SCAN_B)   // 98

// ---------------- device scratch (static; no allocation allowed) -----------
__device__ int   g_is64;
__device__ int   g_src[EE];
__device__ int   g_dst[EE];
__device__ int   g_srt[EE];            // CSR: src sorted by dst
__device__ int   g_deg[NN];
__device__ int   g_row[NN + 1];        // CSR row offsets (exclusive scan)
__device__ int   g_cursor[NN];
__device__ int   g_blk[NSCAN];
__device__ int   g_blkoff[NSCAN];
__device__ float g_dinv[NN];
__device__ float g_h[NN * 16];         // hs = (x@W1)*dinv
__device__ float g_h2[NN * 16];        // zs = relu(agg1+b1)*dinv
__device__ float g_agg[NN * 16];       // agg_z (layer-2 aggregate, scaled)

// ---------------- edge dtype probe (int64 vs int32) ------------------------
__global__ void k_detect(const long long* e) {
    __shared__ int bad;
    if (threadIdx.x == 0) bad = 0;
    __syncthreads();
    long long v = e[threadIdx.x];
    if (v < 0 || v >= (long long)NN) atomicOr(&bad, 1);
    __syncthreads();
    if (threadIdx.x == 0) g_is64 = bad ? 0 : 1;
}

__global__ void k_deg_zero() {
    int i = blockIdx.x * 256 + threadIdx.x;
    if (i < NN) g_deg[i] = 0;
}

// convert edges to int32 and accumulate degree histogram in one pass
__global__ void k_conv_deg(const void* eptr) {
    int i = blockIdx.x * 256 + threadIdx.x;
    int s, d;
    if (g_is64) {
        const long long* e = (const long long*)eptr;
        s = (int)e[i];
        d = (int)e[i + EE];
    } else {
        const int* e = (const int*)eptr;
        s = e[i];
        d = e[i + EE];
    }
    g_src[i] = s;
    g_dst[i] = d;
    atomicAdd(&g_deg[d], 1);
}

// ---------------- 3-phase exclusive scan of g_deg -> g_row -----------------
__global__ void k_scan1() {
    __shared__ int sh[SCAN_B];
    int i = blockIdx.x * SCAN_B + threadIdx.x;
    int v = (i < NN) ? g_deg[i] : 0;
    sh[threadIdx.x] = v;
    __syncthreads();
#pragma unroll
    for (int off = 1; off < SCAN_B; off <<= 1) {
        int t = (threadIdx.x >= off) ? sh[threadIdx.x - off] : 0;
        __syncthreads();
        sh[threadIdx.x] += t;
        __syncthreads();
    }
    if (i < NN) g_row[i] = sh[threadIdx.x] - v;      // exclusive
    if (threadIdx.x == SCAN_B - 1) g_blk[blockIdx.x] = sh[SCAN_B - 1];
}

__global__ void k_scan2() {
    __shared__ int sh[128];
    int t = threadIdx.x;
    int v = (t < NSCAN) ? g_blk[t] : 0;
    sh[t] = v;
    __syncthreads();
#pragma unroll
    for (int off = 1; off < 128; off <<= 1) {
        int u = (t >= off) ? sh[t - off] : 0;
        __syncthreads();
        sh[t] += u;
        __syncthreads();
    }
    if (t < NSCAN) g_blkoff[t] = sh[t] - v;          // exclusive
}

__global__ void k_scan3() {
    int i = blockIdx.x * 256 + threadIdx.x;
    if (i < NN) {
        int r = g_row[i] + g_blkoff[i >> 10];
        g_row[i] = r;
        g_cursor[i] = r;
        g_dinv[i] = rsqrtf((float)g_deg[i] + 1.0f);  // +1 self loop
    }
    if (i == 0) g_row[NN] = EE;
}

// counting-sort fill: CSR payload is src only
__global__ void k_sortfill() {
    int i = blockIdx.x * 256 + threadIdx.x;
    int d = g_dst[i];
    int pos = atomicAdd(&g_cursor[d], 1);
    g_srt[pos] = g_src[i];
}

// ---------------- GEMM1: hs = (x @ W1) * dinv  -----------------------------
__global__ void k_gemm1(const float* __restrict__ x, const float* __restrict__ W1) {
    __shared__ float Ws[512 * 16];
    for (int i = threadIdx.x; i < 512 * 16; i += 256) Ws[i] = W1[i];
    __syncthreads();

    int node = blockIdx.x * 256 + threadIdx.x;
    if (node >= NN) return;

    float acc[16];
#pragma unroll
    for (int j = 0; j < 16; j++) acc[j] = 0.0f;

    const float4* xr = reinterpret_cast<const float4*>(x + (size_t)node * 512);
#pragma unroll 4
    for (int k4 = 0; k4 < 128; k4++) {
        float4 xv = xr[k4];
        const float* wb = &Ws[(k4 * 4) * 16];
#pragma unroll
        for (int c = 0; c < 4; c++) {
            float xc = (c == 0) ? xv.x : (c == 1) ? xv.y : (c == 2) ? xv.z : xv.w;
            const float4* wr = reinterpret_cast<const float4*>(wb + c * 16);
#pragma unroll
            for (int j4 = 0; j4 < 4; j4++) {
                float4 w = wr[j4];
                acc[j4 * 4 + 0] += xc * w.x;
                acc[j4 * 4 + 1] += xc * w.y;
                acc[j4 * 4 + 2] += xc * w.z;
                acc[j4 * 4 + 3] += xc * w.w;
            }
        }
    }
    float s = g_dinv[node];
    float4* hp = reinterpret_cast<float4*>(g_h + (size_t)node * 16);
#pragma unroll
    for (int j4 = 0; j4 < 4; j4++)
        hp[j4] = make_float4(acc[j4 * 4 + 0] * s, acc[j4 * 4 + 1] * s,
                             acc[j4 * 4 + 2] * s, acc[j4 * 4 + 3] * s);
}

// ---------------- CSR aggregation: 4 lanes per node ------------------------
// layer 1: zs = relu(acc*dinv + b1) * dinv  (g_h -> g_h2)
__global__ void k_agg_l1(const float* __restrict__ b1) {
    int t = blockIdx.x * 256 + threadIdx.x;
    int node = t >> 2;
    int j = t & 3;
    if (node >= NN) return;
    int e = g_row[node];
    int end = g_row[node + 1];
    const float4* hs = reinterpret_cast<const float4*>(g_h);
    float4 acc = hs[node * 4 + j];                 // self-loop term
    for (; e + 4 <= end; e += 4) {
        int s0 = g_srt[e], s1 = g_srt[e + 1], s2 = g_srt[e + 2], s3 = g_srt[e + 3];
        float4 a = hs[s0 * 4 + j];
        float4 b = hs[s1 * 4 + j];
        float4 c = hs[s2 * 4 + j];
        float4 d = hs[s3 * 4 + j];
        acc.x += (a.x + b.x) + (c.x + d.x);
        acc.y += (a.y + b.y) + (c.y + d.y);
        acc.z += (a.z + b.z) + (c.z + d.z);
        acc.w += (a.w + b.w) + (c.w + d.w);
    }
    for (; e < end; ++e) {
        int s = g_srt[e];
        float4 a = hs[s * 4 + j];
        acc.x += a.x; acc.y += a.y; acc.z += a.z; acc.w += a.w;
    }
    float di = g_dinv[node];
    float4 bj = __ldg(&reinterpret_cast<const float4*>(b1)[j]);
    float4 z;
    z.x = fmaxf(acc.x * di + bj.x, 0.0f) * di;
    z.y = fmaxf(acc.y * di + bj.y, 0.0f) * di;
    z.z = fmaxf(acc.z * di + bj.z, 0.0f) * di;
    z.w = fmaxf(acc.w * di + bj.w, 0.0f) * di;
    reinterpret_cast<float4*>(g_h2)[node * 4 + j] = z;
}

// layer 2: agg_z = acc*dinv  (g_h2 -> g_agg)
__global__ void k_agg_l2() {
    int t = blockIdx.x * 256 + threadIdx.x;
    int node = t >> 2;
    int j = t & 3;
    if (node >= NN) return;
    int e = g_row[node];
    int end = g_row[node + 1];
    const float4* hs = reinterpret_cast<const float4*>(g_h2);
    float4 acc = hs[node * 4 + j];
    for (; e + 4 <= end; e += 4) {
        int s0 = g_srt[e], s1 = g_srt[e + 1], s2 = g_srt[e + 2], s3 = g_srt[e + 3];
        float4 a = hs[s0 * 4 + j];
        float4 b = hs[s1 * 4 + j];
        float4 c = hs[s2 * 4 + j];
        float4 d = hs[s3 * 4 + j];
        acc.x += (a.x + b.x) + (c.x + d.x);
        acc.y += (a.y + b.y) + (c.y + d.y);
        acc.z += (a.z + b.z) + (c.z + d.z);
        acc.w += (a.w + b.w) + (c.w + d.w);
    }
    for (; e < end; ++e) {
        int s = g_srt[e];
        float4 a = hs[s * 4 + j];
        acc.x += a.x; acc.y += a.y; acc.z += a.z; acc.w += a.w;
    }
    float di = g_dinv[node];
    reinterpret_cast<float4*>(g_agg)[node * 4 + j] =
        make_float4(acc.x * di, acc.y * di, acc.z * di, acc.w * di);
}

// ---------------- final: out = log_softmax(agg_z @ W2 + b2) ----------------
__global__ void k_final(const float* __restrict__ W2, const float* __restrict__ b2,
                        float* __restrict__ out) {
    __shared__ float W2s[16 * 40];
    __shared__ float b2s[40];
    for (int i = threadIdx.x; i < 16 * 40; i += 256) W2s[i] = W2[i];
    if (threadIdx.x < 40) b2s[threadIdx.x] = b2[threadIdx.x];
    __syncthreads();

    int node = blockIdx.x * 256 + threadIdx.x;
    if (node >= NN) return;

    float z[16];
    const float4* ap = reinterpret_cast<const float4*>(g_agg + (size_t)node * 16);
#pragma unroll
    for (int j4 = 0; j4 < 4; j4++) {
        float4 v = ap[j4];
        z[j4 * 4 + 0] = v.x; z[j4 * 4 + 1] = v.y;
        z[j4 * 4 + 2] = v.z; z[j4 * 4 + 3] = v.w;
    }

    float acc[40];
#pragma unroll
    for (int j = 0; j < 40; j++) acc[j] = b2s[j];
#pragma unroll
    for (int k = 0; k < 16; k++) {
        float zk = z[k];
        const float* wr = &W2s[k * 40];
#pragma unroll
        for (int j = 0; j < 40; j++) acc[j] += zk * wr[j];
    }

    float m = acc[0];
#pragma unroll
    for (int j = 1; j < 40; j++) m = fmaxf(m, acc[j]);
    float ssum = 0.0f;
#pragma unroll
    for (int j = 0; j < 40; j++) ssum += expf(acc[j] - m);
    float lse = m + logf(ssum);

    float* op = out + (size_t)node * 40;
#pragma unroll
    for (int j = 0; j < 40; j++) op[j] = acc[j] - lse;
}

// ---------------- launcher --------------------------------------------------
extern "C" void kernel_launch(void* const* d_in, const int* in_sizes, int n_in,
                              void* d_out, int out_size) {
    const float* x  = (const float*)d_in[0];
    const void*  ei = d_in[1];
    const float* W1 = (const float*)d_in[2];
    const float* b1 = (const float*)d_in[3];
    const float* W2 = (const float*)d_in[4];
    const float* b2 = (const float*)d_in[5];
    float* out = (float*)d_out;

    k_detect<<<1, 256>>>((const long long*)ei);
    k_deg_zero<<<NBLK, 256>>>();
    k_conv_deg<<<EBLK, 256>>>(ei);

    k_scan1<<<NSCAN, SCAN_B>>>();
    k_scan2<<<1, 128>>>();
    k_scan3<<<NBLK, 256>>>();

    k_sortfill<<<EBLK, 256>>>();

    k_gemm1<<<NBLK, 256>>>(x, W1);

    int agg_blk = (NN * 4 + 255) / 256;
    k_agg_l1<<<agg_blk, 256>>>(b1);
    k_agg_l2<<<agg_blk, 256>>>();

    k_final<<<NBLK, 256>>>(W2, b2, out);
}

// round 3
// speedup vs baseline: 1.8474x; 1.2179x over previous
#include <cuda_runtime.h>
#include <math.h>

#define NN 100000
#define EE 3200000
#define NBLK ((NN + 255) / 256)
#define EBLK (EE / 256)
#define SCAN_B 1024
#define NSCAN ((NN + SCAN_B - 1) / SCAN_B)   // 98

// ---------------- device scratch (static; no allocation allowed) -----------
__device__ int   g_is64;
__device__ int   g_srt[EE];            // CSR: src sorted by dst
__device__ int   g_deg[NN];
__device__ int   g_row[NN + 1];        // CSR row offsets (exclusive scan)
__device__ int   g_cursor[NN];
__device__ int   g_blk[NSCAN];
__device__ int   g_blkoff[NSCAN];
__device__ float g_dinv[NN];
__device__ float g_h[NN * 16];         // h = x@W1 (unscaled), then scaled by dinv
__device__ float g_h2[NN * 16];        // zs = relu(agg1+b1)*dinv
__device__ float g_agg[NN * 16];       // agg_z

// ---------------- edge dtype probe (int64 vs int32) ------------------------
__global__ void k_detect(const long long* e) {
    __shared__ int bad;
    if (threadIdx.x == 0) bad = 0;
    __syncthreads();
    long long v = e[threadIdx.x];
    if (v < 0 || v >= (long long)NN) atomicOr(&bad, 1);
    __syncthreads();
    if (threadIdx.x == 0) g_is64 = bad ? 0 : 1;
}

__global__ void k_deg_zero() {
    int i = blockIdx.x * 256 + threadIdx.x;
    if (i < NN) g_deg[i] = 0;
}

// degree histogram: reads only the dst half of edge_index
__global__ void k_deg(const void* eptr) {
    int i = blockIdx.x * 256 + threadIdx.x;
    int d;
    if (g_is64) d = (int)((const long long*)eptr)[i + EE];
    else        d = ((const int*)eptr)[i + EE];
    atomicAdd(&g_deg[d], 1);
}

// ---------------- exclusive scan of g_deg -> g_row (warp-shuffle) ----------
__global__ void k_scan1() {
    __shared__ int wsum[32];
    int i = blockIdx.x * SCAN_B + threadIdx.x;
    int v = (i < NN) ? g_deg[i] : 0;
    int lane = threadIdx.x & 31, warp = threadIdx.x >> 5;
    int s = v;
#pragma unroll
    for (int off = 1; off < 32; off <<= 1) {
        int t = __shfl_up_sync(0xffffffffu, s, off);
        if (lane >= off) s += t;
    }
    if (lane == 31) wsum[warp] = s;
    __syncthreads();
    if (warp == 0) {
        int w = wsum[lane];
#pragma unroll
        for (int off = 1; off < 32; off <<= 1) {
            int t = __shfl_up_sync(0xffffffffu, w, off);
            if (lane >= off) w += t;
        }
        wsum[lane] = w;
    }
    __syncthreads();
    int incl = s + (warp ? wsum[warp - 1] : 0);
    if (i < NN) g_row[i] = incl - v;                  // exclusive
    if (threadIdx.x == SCAN_B - 1) g_blk[blockIdx.x] = incl;
}

__global__ void k_scan2() {
    __shared__ int sh[128];
    int t = threadIdx.x;
    int v = (t < NSCAN) ? g_blk[t] : 0;
    sh[t] = v;
    __syncthreads();
#pragma unroll
    for (int off = 1; off < 128; off <<= 1) {
        int u = (t >= off) ? sh[t - off] : 0;
        __syncthreads();
        sh[t] += u;
        __syncthreads();
    }
    if (t < NSCAN) g_blkoff[t] = sh[t] - v;
}

__global__ void k_scan3() {
    int i = blockIdx.x * 256 + threadIdx.x;
    if (i < NN) {
        int r = g_row[i] + g_blkoff[i >> 10];
        g_row[i] = r;
        g_cursor[i] = r;
        g_dinv[i] = rsqrtf((float)g_deg[i] + 1.0f);   // +1 self loop
    }
    if (i == 0) g_row[NN] = EE;
}

// counting-sort fill (converts int64 inline): CSR payload is src only
__global__ void k_sortfill(const void* eptr) {
    int i = blockIdx.x * 256 + threadIdx.x;
    int s, d;
    if (g_is64) {
        const long long* e = (const long long*)eptr;
        s = (int)e[i];
        d = (int)e[i + EE];
    } else {
        const int* e = (const int*)eptr;
        s = e[i];
        d = e[i + EE];
    }
    int pos = atomicAdd(&g_cursor[d], 1);
    g_srt[pos] = s;
}

// ---------------- GEMM1: h = x @ W1 (unscaled; runs on side stream) --------
__global__ void k_gemm1(const float* __restrict__ x, const float* __restrict__ W1) {
    __shared__ float Ws[512 * 16];
    for (int i = threadIdx.x; i < 512 * 16; i += 256) Ws[i] = W1[i];
    __syncthreads();

    int node = blockIdx.x * 256 + threadIdx.x;
    if (node >= NN) return;

    float acc[16];
#pragma unroll
    for (int j = 0; j < 16; j++) acc[j] = 0.0f;

    const float4* xr = reinterpret_cast<const float4*>(x + (size_t)node * 512);
#pragma unroll 8
    for (int k4 = 0; k4 < 128; k4++) {
        float4 xv = xr[k4];
        const float* wb = &Ws[(k4 * 4) * 16];
#pragma unroll
        for (int c = 0; c < 4; c++) {
            float xc = (c == 0) ? xv.x : (c == 1) ? xv.y : (c == 2) ? xv.z : xv.w;
            const float4* wr = reinterpret_cast<const float4*>(wb + c * 16);
#pragma unroll
            for (int j4 = 0; j4 < 4; j4++) {
                float4 w = wr[j4];
                acc[j4 * 4 + 0] += xc * w.x;
                acc[j4 * 4 + 1] += xc * w.y;
                acc[j4 * 4 + 2] += xc * w.z;
                acc[j4 * 4 + 3] += xc * w.w;
            }
        }
    }
    float4* hp = reinterpret_cast<float4*>(g_h + (size_t)node * 16);
#pragma unroll
    for (int j4 = 0; j4 < 4; j4++)
        hp[j4] = make_float4(acc[j4 * 4 + 0], acc[j4 * 4 + 1],
                             acc[j4 * 4 + 2], acc[j4 * 4 + 3]);
}

// scale h by dinv after join
__global__ void k_scale() {
    int t = blockIdx.x * 256 + threadIdx.x;
    int node = t >> 2;
    if (node >= NN) return;
    float s = g_dinv[node];
    float4* hp = reinterpret_cast<float4*>(g_h);
    float4 v = hp[t];
    hp[t] = make_float4(v.x * s, v.y * s, v.z * s, v.w * s);
}

// ---------------- CSR aggregation: 4 lanes per node ------------------------
__global__ void k_agg_l1(const float* __restrict__ b1) {
    int t = blockIdx.x * 256 + threadIdx.x;
    int node = t >> 2;
    int j = t & 3;
    if (node >= NN) return;
    int e = g_row[node];
    int end = g_row[node + 1];
    const float4* hs = reinterpret_cast<const float4*>(g_h);
    float4 acc = hs[node * 4 + j];                 // self-loop term
    for (; e + 4 <= end; e += 4) {
        int s0 = g_srt[e], s1 = g_srt[e + 1], s2 = g_srt[e + 2], s3 = g_srt[e + 3];
        float4 a = hs[s0 * 4 + j];
        float4 b = hs[s1 * 4 + j];
        float4 c = hs[s2 * 4 + j];
        float4 d = hs[s3 * 4 + j];
        acc.x += (a.x + b.x) + (c.x + d.x);
        acc.y += (a.y + b.y) + (c.y + d.y);
        acc.z += (a.z + b.z) + (c.z + d.z);
        acc.w += (a.w + b.w) + (c.w + d.w);
    }
    for (; e < end; ++e) {
        int s = g_srt[e];
        float4 a = hs[s * 4 + j];
        acc.x += a.x; acc.y += a.y; acc.z += a.z; acc.w += a.w;
    }
    float di = g_dinv[node];
    float4 bj = __ldg(&reinterpret_cast<const float4*>(b1)[j]);
    float4 z;
    z.x = fmaxf(acc.x * di + bj.x, 0.0f) * di;
    z.y = fmaxf(acc.y * di + bj.y, 0.0f) * di;
    z.z = fmaxf(acc.z * di + bj.z, 0.0f) * di;
    z.w = fmaxf(acc.w * di + bj.w, 0.0f) * di;
    reinterpret_cast<float4*>(g_h2)[node * 4 + j] = z;
}

__global__ void k_agg_l2() {
    int t = blockIdx.x * 256 + threadIdx.x;
    int node = t >> 2;
    int j = t & 3;
    if (node >= NN) return;
    int e = g_row[node];
    int end = g_row[node + 1];
    const float4* hs = reinterpret_cast<const float4*>(g_h2);
    float4 acc = hs[node * 4 + j];
    for (; e + 4 <= end; e += 4) {
        int s0 = g_srt[e], s1 = g_srt[e + 1], s2 = g_srt[e + 2], s3 = g_srt[e + 3];
        float4 a = hs[s0 * 4 + j];
        float4 b = hs[s1 * 4 + j];
        float4 c = hs[s2 * 4 + j];
        float4 d = hs[s3 * 4 + j];
        acc.x += (a.x + b.x) + (c.x + d.x);
        acc.y += (a.y + b.y) + (c.y + d.y);
        acc.z += (a.z + b.z) + (c.z + d.z);
        acc.w += (a.w + b.w) + (c.w + d.w);
    }
    for (; e < end; ++e) {
        int s = g_srt[e];
        float4 a = hs[s * 4 + j];
        acc.x += a.x; acc.y += a.y; acc.z += a.z; acc.w += a.w;
    }
    float di = g_dinv[node];
    reinterpret_cast<float4*>(g_agg)[node * 4 + j] =
        make_float4(acc.x * di, acc.y * di, acc.z * di, acc.w * di);
}

// ---------------- final: out = log_softmax(agg_z @ W2 + b2) ----------------
__global__ void k_final(const float* __restrict__ W2, const float* __restrict__ b2,
                        float* __restrict__ out) {
    __shared__ float W2s[16 * 40];
    __shared__ float b2s[40];
    for (int i = threadIdx.x; i < 16 * 40; i += 256) W2s[i] = W2[i];
    if (threadIdx.x < 40) b2s[threadIdx.x] = b2[threadIdx.x];
    __syncthreads();

    int node = blockIdx.x * 256 + threadIdx.x;
    if (node >= NN) return;

    float z[16];
    const float4* ap = reinterpret_cast<const float4*>(g_agg + (size_t)node * 16);
#pragma unroll
    for (int j4 = 0; j4 < 4; j4++) {
        float4 v = ap[j4];
        z[j4 * 4 + 0] = v.x; z[j4 * 4 + 1] = v.y;
        z[j4 * 4 + 2] = v.z; z[j4 * 4 + 3] = v.w;
    }

    float acc[40];
#pragma unroll
    for (int j = 0; j < 40; j++) acc[j] = b2s[j];
#pragma unroll
    for (int k = 0; k < 16; k++) {
        float zk = z[k];
        const float* wr = &W2s[k * 40];
#pragma unroll
        for (int j = 0; j < 40; j++) acc[j] += zk * wr[j];
    }

    float m = acc[0];
#pragma unroll
    for (int j = 1; j < 40; j++) m = fmaxf(m, acc[j]);
    float ssum = 0.0f;
#pragma unroll
    for (int j = 0; j < 40; j++) ssum += expf(acc[j] - m);
    float lse = m + logf(ssum);

    float* op = out + (size_t)node * 40;
#pragma unroll
    for (int j = 0; j < 40; j++) op[j] = acc[j] - lse;
}

// ---------------- launcher with fork/join onto a side stream ---------------
static cudaStream_t g_s2 = 0;
static cudaEvent_t  g_ev_fork = 0, g_ev_join = 0;

extern "C" void kernel_launch(void* const* d_in, const int* in_sizes, int n_in,
                              void* d_out, int out_size) {
    const float* x  = (const float*)d_in[0];
    const void*  ei = d_in[1];
    const float* W1 = (const float*)d_in[2];
    const float* b1 = (const float*)d_in[3];
    const float* W2 = (const float*)d_in[4];
    const float* b2 = (const float*)d_in[5];
    float* out = (float*)d_out;

    if (!g_s2) {   // one-time infra setup (first call is uncaptured)
        cudaStreamCreateWithFlags(&g_s2, cudaStreamNonBlocking);
        cudaEventCreateWithFlags(&g_ev_fork, cudaEventDisableTiming);
        cudaEventCreateWithFlags(&g_ev_join, cudaEventDisableTiming);
    }

    // fork: GEMM1 runs concurrently with the CSR build
    cudaEventRecord(g_ev_fork, 0);
    cudaStreamWaitEvent(g_s2, g_ev_fork, 0);
    k_gemm1<<<NBLK, 256, 0, g_s2>>>(x, W1);
    cudaEventRecord(g_ev_join, g_s2);

    // CSR build chain on the main stream
    k_detect<<<1, 256>>>((const long long*)ei);
    k_deg_zero<<<NBLK, 256>>>();
    k_deg<<<EBLK, 256>>>(ei);
    k_scan1<<<NSCAN, SCAN_B>>>();
    k_scan2<<<1, 128>>>();
    k_scan3<<<NBLK, 256>>>();
    k_sortfill<<<EBLK, 256>>>(ei);

    // join, then the dependent chain
    cudaStreamWaitEvent(0, g_ev_join, 0);
    int blk4 = (NN * 4 + 255) / 256;
    k_scale<<<blk4, 256>>>();
    k_agg_l1<<<blk4, 256>>>(b1);
    k_agg_l2<<<blk4, 256>>>();
    k_final<<<NBLK, 256>>>(W2, b2, out);
}